// round 16
// baseline (speedup 1.0000x reference)
#include <cuda_runtime.h>
#include <cuda_bf16.h>
#include <cstdint>

#define N_NODES 100000
#define N_EDGES 600000
#define C 128
#define SCAN_B 1024
#define N_SCAN_BLOCKS ((N_NODES + SCAN_B - 1) / SCAN_B)   // 98
#define CNT_BLOCKS ((N_EDGES + 255) / 256)                // 2344
#define TILE_M 128
#define N_TILES ((N_NODES + TILE_M - 1) / TILE_M)         // 782
#define GRID_FINAL 148

// ---------------- scratch (static device globals) ---------------------------
__device__ __align__(16) float g_W[C * C];       // evolved GCN weight, W[k][n]
__device__ uint32_t g_Wth[C * (C / 2)];          // W^T hi bf16 pairs: [n][k/2]
__device__ uint32_t g_Wtl[C * (C / 2)];          // W^T lo bf16 pairs: [n][k/2]
__device__ float g_dinv[N_NODES];                // 1 -> wdeg -> rsqrt(wdeg)
__device__ int   g_cnt[N_NODES];
__device__ int   g_off[N_NODES + 1];
__device__ int   g_bsum[N_SCAN_BLOCKS];
__device__ int   g_boff[N_SCAN_BLOCKS];
__device__ __align__(8) int2 g_csr[N_EDGES];     // packed (row, norm-bits)
__device__ int   g_is64;
__device__ int   g_done_w = 0;
__device__ int   g_done_s = 0;

__device__ __forceinline__ int load_idx(const void* ei, long long pos, int is64) {
    return is64 ? (int)((const long long*)ei)[pos] : ((const int*)ei)[pos];
}

// ---------------- 1. deg/cnt init + dtype detect (block 0) ------------------
__global__ void __launch_bounds__(256)
deg_init(const unsigned* __restrict__ ei_w) {
    int i = blockIdx.x * blockDim.x + threadIdx.x;
    if (i < N_NODES) { g_dinv[i] = 1.0f; g_cnt[i] = 0; }
    if (blockIdx.x == 0 && threadIdx.x < 32) {
        unsigned w = ei_w[2 * threadIdx.x + 1];
        unsigned nz = __ballot_sync(0xffffffffu, w != 0u);
        if (threadIdx.x == 0) g_is64 = (nz == 0u) ? 1 : 0;
    }
}

// ---------------- 2. GRU evolution of W0 + W split (last block) -------------
__global__ void __launch_bounds__(128)
gru_kernel(const float* __restrict__ W0,
           const float* __restrict__ Wih,
           const float* __restrict__ Whh,
           const float* __restrict__ bih,
           const float* __restrict__ bhh) {
    __shared__ float w0row[C];
    __shared__ bool is_last;
    int i = blockIdx.x;
    int t = threadIdx.x;
    w0row[t] = W0[i * C + t];
    __syncthreads();

    float gir = bih[t], giz = bih[t + C], gin = bih[t + 2 * C];
    float ghr = bhh[t], ghz = bhh[t + C], ghn = bhh[t + 2 * C];
    const float* wr = Wih + (size_t)t * C;
    const float* wz = Wih + (size_t)(t + C) * C;
    const float* wn = Wih + (size_t)(t + 2 * C) * C;
    const float* hr = Whh + (size_t)t * C;
    const float* hz = Whh + (size_t)(t + C) * C;
    const float* hn = Whh + (size_t)(t + 2 * C) * C;
    #pragma unroll 4
    for (int k = 0; k < C; k++) {
        float a = w0row[k];
        gir += a * wr[k]; giz += a * wz[k]; gin += a * wn[k];
        ghr += a * hr[k]; ghz += a * hz[k]; ghn += a * hn[k];
    }
    float r    = 1.0f / (1.0f + expf(-(gir + ghr)));
    float z    = 1.0f / (1.0f + expf(-(giz + ghz)));
    float cand = tanhf(gin + r * ghn);
    g_W[i * C + t] = (1.0f - z) * cand + z * w0row[t];

    __threadfence();
    __syncthreads();
    if (t == 0) is_last = (atomicAdd(&g_done_w, 1) == gridDim.x - 1);
    __syncthreads();
    if (is_last) {
        int n = t;     // B[n][k] = W[k][n], hi/lo bf16, n-major k-paired
        for (int j = 0; j < C / 2; j++) {
            float w0 = g_W[(2 * j) * C + n];
            float w1 = g_W[(2 * j + 1) * C + n];
            __nv_bfloat162 h = __floats2bfloat162_rn(w0, w1);
            float2 hb = __bfloat1622float2(h);
            __nv_bfloat162 l = __floats2bfloat162_rn(w0 - hb.x, w1 - hb.y);
            g_Wth[n * 64 + j] = *(uint32_t*)&h;
            g_Wtl[n * 64 + j] = *(uint32_t*)&l;
        }
        if (t == 0) g_done_w = 0;
    }
}

// ---------------- 3. degree + count ------------------------------------------
__global__ void __launch_bounds__(256)
count_kernel(const void* __restrict__ ei, const float* __restrict__ ew) {
    int e = blockIdx.x * blockDim.x + threadIdx.x;
    if (e < N_EDGES) {
        int is64 = g_is64;
        int c = load_idx(ei, (long long)N_EDGES + e, is64);
        atomicAdd(&g_dinv[c], ew[e]);
        atomicAdd(&g_cnt[c], 1);
    }
}

// ---------------- 4. scan + last-block block-sum scan -----------------------
__global__ void __launch_bounds__(1024)
scan_a() {
    __shared__ int warpsum[48];
    __shared__ bool is_last;
    int i = blockIdx.x * SCAN_B + threadIdx.x;
    int lane = threadIdx.x & 31, wid = threadIdx.x >> 5;
    int v = 0;
    if (i < N_NODES) {
        v = g_cnt[i];
        g_cnt[i] = 0;
        g_dinv[i] = rsqrtf(g_dinv[i]);
    }
    int incl = v;
    #pragma unroll
    for (int o = 1; o < 32; o <<= 1) {
        int t = __shfl_up_sync(0xffffffffu, incl, o);
        if (lane >= o) incl += t;
    }
    if (lane == 31) warpsum[wid] = incl;
    __syncthreads();
    if (wid == 0) {
        int ws = warpsum[lane];
        int wincl = ws;
        #pragma unroll
        for (int o = 1; o < 32; o <<= 1) {
            int t = __shfl_up_sync(0xffffffffu, wincl, o);
            if (lane >= o) wincl += t;
        }
        warpsum[lane] = wincl - ws;
        if (lane == 31) g_bsum[blockIdx.x] = wincl;
    }
    __syncthreads();
    if (i < N_NODES) g_off[i] = warpsum[wid] + incl - v;

    __threadfence();
    if (threadIdx.x == 0) is_last = (atomicAdd(&g_done_s, 1) == gridDim.x - 1);
    __syncthreads();
    if (is_last) {
        int bincl = 0, bv = 0;
        if (threadIdx.x < 128) {
            bv = (threadIdx.x < N_SCAN_BLOCKS) ? g_bsum[threadIdx.x] : 0;
            bincl = bv;
            #pragma unroll
            for (int o = 1; o < 32; o <<= 1) {
                int t = __shfl_up_sync(0xffffffffu, bincl, o);
                if (lane >= o) bincl += t;
            }
            if (lane == 31) warpsum[32 + wid] = bincl;
        }
        __syncthreads();
        if (threadIdx.x < N_SCAN_BLOCKS) {
            int woff = 0;
            for (int w = 0; w < wid; w++) woff += warpsum[32 + w];
            g_boff[threadIdx.x] = woff + bincl - bv;
        }
        if (threadIdx.x == 0) g_done_s = 0;
    }
}

// ---------------- 5. CSR fill (packed int2) ----------------------------------
__global__ void __launch_bounds__(256)
fill_kernel(const void* __restrict__ ei, const float* __restrict__ ew) {
    int e = blockIdx.x * blockDim.x + threadIdx.x;
    if (e < N_EDGES) {
        int is64 = g_is64;
        int r = load_idx(ei, e, is64);
        int c = load_idx(ei, (long long)N_EDGES + e, is64);
        float nv = g_dinv[r] * ew[e] * g_dinv[c];
        int pos = g_off[c] + g_boff[c >> 10] + atomicAdd(&g_cnt[c], 1);
        g_csr[pos] = make_int2(r, __float_as_int(nv));
    }
}

// ---------------- 6. persistent producer/consumer final kernel ---------------
// 148 blocks x 512 threads, 1 block/SM. Warps 0-7 gather tiles of 128 rows
// into a 2-deep A ring; warps 8-15 run the bf16-split MMA + ReLU + cls on the
// previous tile concurrently. Named barriers: full = 1+buf, empty = 3+buf.
__device__ __forceinline__ void mma_bf16(float& c0, float& c1, float& c2, float& c3,
                                         uint32_t a0, uint32_t a1, uint32_t a2, uint32_t a3,
                                         uint32_t b0, uint32_t b1) {
    asm volatile("mma.sync.aligned.m16n8k16.row.col.f32.bf16.bf16.f32 "
                 "{%0,%1,%2,%3}, {%4,%5,%6,%7}, {%8,%9}, {%0,%1,%2,%3};"
                 : "+f"(c0), "+f"(c1), "+f"(c2), "+f"(c3)
                 : "r"(a0), "r"(a1), "r"(a2), "r"(a3), "r"(b0), "r"(b1));
}

#define LDW 68
#define ABUF (2 * TILE_M * LDW)     // one buffer: hi + lo, u32 units

__device__ __forceinline__ float4 gacc4(float4 a, float n, float4 v) {
    a.x += n * v.x; a.y += n * v.y; a.z += n * v.z; a.w += n * v.w;
    return a;
}

__global__ void __launch_bounds__(512, 1)
final_kernel(const float* __restrict__ x,
             const float* __restrict__ clsw,
             const float* __restrict__ clsb,
             float* __restrict__ out) {
    extern __shared__ char sh[];
    uint32_t* sWh = (uint32_t*)sh;                   // [128][LDW]
    uint32_t* sWl = sWh + C * LDW;                   // [128][LDW]
    uint32_t* sA  = sWl + C * LDW;                   // 2 bufs x (hi[128][LDW], lo[128][LDW])
    float*    scw = (float*)(sA + 2 * ABUF);         // [128]

    const int tid = threadIdx.x;
    const int warp = tid >> 5, lane = tid & 31;
    const int g = lane >> 2, t = lane & 3;
    const float4* x4 = (const float4*)x;
    const float cb = clsb[0];

    // ---- stage W hi/lo + cls once per block ----
    for (int i = tid; i < C * (C / 2); i += 512) {
        int n = i >> 6, j = i & 63;
        sWh[n * LDW + j] = g_Wth[i];
        sWl[n * LDW + j] = g_Wtl[i];
    }
    if (tid < C) scw[tid] = clsw[tid];
    __syncthreads();

    if (warp < 8) {
        // =============== producer: gather 16 rows/warp per tile ===============
        int it = 0;
        for (int tile = blockIdx.x; tile < N_TILES; tile += GRID_FINAL, it++) {
            int buf = it & 1;
            uint32_t* xsh = sA + buf * ABUF;
            uint32_t* xsl = xsh + TILE_M * LDW;
            if (it >= 2)
                asm volatile("bar.sync %0, 512;" :: "r"(3 + buf) : "memory");

            const int row0 = tile * TILE_M;
            const int n0w = row0 + warp * 16;

            int offv = N_EDGES;
            if (lane < 17) {
                int nn = n0w + lane;
                offv = (nn < N_NODES) ? (g_off[nn] + g_boff[nn >> 10]) : N_EDGES;
            }

            #pragma unroll
            for (int grp = 0; grp < 4; grp++) {
                float4 acc[4];
                const int lr0 = warp * 16 + grp * 4;

                #pragma unroll
                for (int r = 0; r < 4; r++) {
                    int node = row0 + lr0 + r;
                    acc[r] = make_float4(0.f, 0.f, 0.f, 0.f);
                    if (node < N_NODES) {
                        float dv = g_dinv[node];
                        acc[r] = gacc4(acc[r], dv * dv, x4[(size_t)node * 32 + lane]);
                    }
                }

                #pragma unroll
                for (int r = 0; r < 4; r++) {
                    int beg = __shfl_sync(0xffffffffu, offv, grp * 4 + r);
                    int end = __shfl_sync(0xffffffffu, offv, grp * 4 + r + 1);
                    for (int k = beg; k < end; k += 4) {
                        int e1 = (k + 1 < end) ? k + 1 : k;
                        int e2 = (k + 2 < end) ? k + 2 : k;
                        int e3 = (k + 3 < end) ? k + 3 : k;
                        int2 c0 = g_csr[k],  c1 = g_csr[e1];
                        int2 c2 = g_csr[e2], c3 = g_csr[e3];
                        float m0 = __int_as_float(c0.y);
                        float m1 = (k + 1 < end) ? __int_as_float(c1.y) : 0.f;
                        float m2 = (k + 2 < end) ? __int_as_float(c2.y) : 0.f;
                        float m3 = (k + 3 < end) ? __int_as_float(c3.y) : 0.f;
                        float4 v0 = x4[(size_t)c0.x * 32 + lane];
                        float4 v1 = x4[(size_t)c1.x * 32 + lane];
                        float4 v2 = x4[(size_t)c2.x * 32 + lane];
                        float4 v3 = x4[(size_t)c3.x * 32 + lane];
                        acc[r] = gacc4(gacc4(gacc4(gacc4(acc[r], m0, v0), m1, v1), m2, v2), m3, v3);
                    }
                }

                #pragma unroll
                for (int r = 0; r < 4; r++) {
                    int lrow = lr0 + r;
                    __nv_bfloat162 h0 = __floats2bfloat162_rn(acc[r].x, acc[r].y);
                    __nv_bfloat162 h1 = __floats2bfloat162_rn(acc[r].z, acc[r].w);
                    float2 f0 = __bfloat1622float2(h0), f1 = __bfloat1622float2(h1);
                    __nv_bfloat162 l0 = __floats2bfloat162_rn(acc[r].x - f0.x, acc[r].y - f0.y);
                    __nv_bfloat162 l1 = __floats2bfloat162_rn(acc[r].z - f1.x, acc[r].w - f1.y);
                    xsh[lrow * LDW + lane * 2]     = *(uint32_t*)&h0;
                    xsh[lrow * LDW + lane * 2 + 1] = *(uint32_t*)&h1;
                    xsl[lrow * LDW + lane * 2]     = *(uint32_t*)&l0;
                    xsl[lrow * LDW + lane * 2 + 1] = *(uint32_t*)&l1;
                }
            }

            __threadfence_block();
            asm volatile("bar.arrive %0, 512;" :: "r"(1 + buf) : "memory");
        }
    } else {
        // =============== consumer: 16 rows x 128 cols per warp ===============
        const int cw = warp - 8;          // 0..7
        const int m0 = cw * 16;
        int it = 0;
        for (int tile = blockIdx.x; tile < N_TILES; tile += GRID_FINAL, it++) {
            int buf = it & 1;
            uint32_t* xsh = sA + buf * ABUF;
            uint32_t* xsl = xsh + TILE_M * LDW;
            asm volatile("bar.sync %0, 512;" :: "r"(1 + buf) : "memory");

            float acc[16][4];
            #pragma unroll
            for (int nt = 0; nt < 16; nt++)
                acc[nt][0] = acc[nt][1] = acc[nt][2] = acc[nt][3] = 0.f;

            #pragma unroll
            for (int kt = 0; kt < 8; kt++) {
                int abase = (m0 + g) * LDW + kt * 8 + t;
                uint32_t ah0 = xsh[abase],     ah1 = xsh[abase + 8 * LDW];
                uint32_t ah2 = xsh[abase + 4], ah3 = xsh[abase + 8 * LDW + 4];
                uint32_t al0 = xsl[abase],     al1 = xsl[abase + 8 * LDW];
                uint32_t al2 = xsl[abase + 4], al3 = xsl[abase + 8 * LDW + 4];
                #pragma unroll
                for (int nt = 0; nt < 16; nt++) {
                    int n = nt * 8 + g;
                    int bbase = n * LDW + kt * 8 + t;
                    uint32_t bh0 = sWh[bbase], bh1 = sWh[bbase + 4];
                    uint32_t bl0 = sWl[bbase], bl1 = sWl[bbase + 4];
                    mma_bf16(acc[nt][0], acc[nt][1], acc[nt][2], acc[nt][3],
                             ah0, ah1, ah2, ah3, bh0, bh1);
                    mma_bf16(acc[nt][0], acc[nt][1], acc[nt][2], acc[nt][3],
                             ah0, ah1, ah2, ah3, bl0, bl1);
                    mma_bf16(acc[nt][0], acc[nt][1], acc[nt][2], acc[nt][3],
                             al0, al1, al2, al3, bh0, bh1);
                }
            }

            __threadfence_block();
            asm volatile("bar.arrive %0, 512;" :: "r"(3 + buf) : "memory");

            // epilogue: relu + cls dot, quad reduce, direct store
            float p0 = 0.f, p1 = 0.f;
            #pragma unroll
            for (int nt = 0; nt < 16; nt++) {
                int col = nt * 8 + 2 * t;
                float w0 = scw[col], w1 = scw[col + 1];
                p0 += fmaxf(acc[nt][0], 0.f) * w0 + fmaxf(acc[nt][1], 0.f) * w1;
                p1 += fmaxf(acc[nt][2], 0.f) * w0 + fmaxf(acc[nt][3], 0.f) * w1;
            }
            p0 += __shfl_xor_sync(0xffffffffu, p0, 1);
            p0 += __shfl_xor_sync(0xffffffffu, p0, 2);
            p1 += __shfl_xor_sync(0xffffffffu, p1, 1);
            p1 += __shfl_xor_sync(0xffffffffu, p1, 2);
            if (t == 0) {
                int row0 = tile * TILE_M;
                int ra = row0 + m0 + g, rb = ra + 8;
                if (ra < N_NODES) out[ra] = p0 + cb;
                if (rb < N_NODES) out[rb] = p1 + cb;
            }
        }
    }
}

// ---------------- launcher ---------------------------------------------------
extern "C" void kernel_launch(void* const* d_in, const int* in_sizes, int n_in,
                              void* d_out, int out_size) {
    const float* x    = (const float*)d_in[0];
    const void*  ei   = d_in[1];
    const float* ew   = (const float*)d_in[2];
    const float* W0   = (const float*)d_in[3];
    const float* Wih  = (const float*)d_in[4];
    const float* Whh  = (const float*)d_in[5];
    const float* bih  = (const float*)d_in[6];
    const float* bhh  = (const float*)d_in[7];
    const float* clsw = (const float*)d_in[8];
    const float* clsb = (const float*)d_in[9];
    float* out = (float*)d_out;

    deg_init<<<(N_NODES + 255) / 256, 256>>>((const unsigned*)ei);
    gru_kernel<<<C, C>>>(W0, Wih, Whh, bih, bhh);
    count_kernel<<<CNT_BLOCKS, 256>>>(ei, ew);
    scan_a<<<N_SCAN_BLOCKS, SCAN_B>>>();
    fill_kernel<<<CNT_BLOCKS, 256>>>(ei, ew);

    const int SMEM = (2 * C * LDW + 2 * ABUF + C) * (int)sizeof(float);  // ~209.4 KB
    cudaFuncSetAttribute(final_kernel, cudaFuncAttributeMaxDynamicSharedMemorySize, SMEM);
    final_kernel<<<GRID_FINAL, 512, SMEM>>>(x, clsw, clsb, out);
}

// round 17
// speedup vs baseline: 1.1816x; 1.1816x over previous
#include <cuda_runtime.h>
#include <cuda_bf16.h>
#include <cstdint>

#define N_NODES 100000
#define N_EDGES 600000
#define C 128
#define SCAN_B 1024
#define N_SCAN_BLOCKS ((N_NODES + SCAN_B - 1) / SCAN_B)   // 98
#define CNT_BLOCKS ((N_EDGES + 255) / 256)                // 2344

// ---------------- scratch (static device globals) ---------------------------
__device__ __align__(16) float g_W[C * C];       // evolved GCN weight, W[k][n]
__device__ uint32_t g_Wth[C * (C / 2)];          // W^T hi bf16 pairs: [n][k/2]
__device__ uint32_t g_Wtl[C * (C / 2)];          // W^T lo bf16 pairs: [n][k/2]
__device__ float g_dinv[N_NODES];                // 1 -> wdeg -> rsqrt(wdeg)
__device__ int   g_cnt[N_NODES];
__device__ int   g_off[N_NODES + 1];
__device__ int   g_bsum[N_SCAN_BLOCKS];
__device__ int   g_boff[N_SCAN_BLOCKS];
__device__ __align__(8) int2 g_csr[N_EDGES];     // packed (row, norm-bits)
__device__ int   g_is64;
__device__ int   g_done_w = 0;
__device__ int   g_done_s = 0;

__device__ __forceinline__ int load_idx(const void* ei, long long pos, int is64) {
    return is64 ? (int)((const long long*)ei)[pos] : ((const int*)ei)[pos];
}

// ---------------- 1. deg/cnt init + dtype detect (block 0) ------------------
__global__ void __launch_bounds__(256)
deg_init(const unsigned* __restrict__ ei_w) {
    int i = blockIdx.x * blockDim.x + threadIdx.x;
    if (i < N_NODES) { g_dinv[i] = 1.0f; g_cnt[i] = 0; }
    if (blockIdx.x == 0 && threadIdx.x < 32) {
        unsigned w = ei_w[2 * threadIdx.x + 1];
        unsigned nz = __ballot_sync(0xffffffffu, w != 0u);
        if (threadIdx.x == 0) g_is64 = (nz == 0u) ? 1 : 0;
    }
}

// ---------------- 2. GRU evolution of W0 + W split (last block) -------------
__global__ void __launch_bounds__(128)
gru_kernel(const float* __restrict__ W0,
           const float* __restrict__ Wih,
           const float* __restrict__ Whh,
           const float* __restrict__ bih,
           const float* __restrict__ bhh) {
    __shared__ float w0row[C];
    __shared__ bool is_last;
    int i = blockIdx.x;
    int t = threadIdx.x;
    w0row[t] = W0[i * C + t];
    __syncthreads();

    float gir = bih[t], giz = bih[t + C], gin = bih[t + 2 * C];
    float ghr = bhh[t], ghz = bhh[t + C], ghn = bhh[t + 2 * C];
    const float* wr = Wih + (size_t)t * C;
    const float* wz = Wih + (size_t)(t + C) * C;
    const float* wn = Wih + (size_t)(t + 2 * C) * C;
    const float* hr = Whh + (size_t)t * C;
    const float* hz = Whh + (size_t)(t + C) * C;
    const float* hn = Whh + (size_t)(t + 2 * C) * C;
    #pragma unroll 4
    for (int k = 0; k < C; k++) {
        float a = w0row[k];
        gir += a * wr[k]; giz += a * wz[k]; gin += a * wn[k];
        ghr += a * hr[k]; ghz += a * hz[k]; ghn += a * hn[k];
    }
    float r    = 1.0f / (1.0f + expf(-(gir + ghr)));
    float z    = 1.0f / (1.0f + expf(-(giz + ghz)));
    float cand = tanhf(gin + r * ghn);
    g_W[i * C + t] = (1.0f - z) * cand + z * w0row[t];

    __threadfence();
    __syncthreads();
    if (t == 0) is_last = (atomicAdd(&g_done_w, 1) == gridDim.x - 1);
    __syncthreads();
    if (is_last) {
        int n = t;     // B[n][k] = W[k][n], hi/lo bf16, n-major k-paired
        for (int j = 0; j < C / 2; j++) {
            float w0 = g_W[(2 * j) * C + n];
            float w1 = g_W[(2 * j + 1) * C + n];
            __nv_bfloat162 h = __floats2bfloat162_rn(w0, w1);
            float2 hb = __bfloat1622float2(h);
            __nv_bfloat162 l = __floats2bfloat162_rn(w0 - hb.x, w1 - hb.y);
            g_Wth[n * 64 + j] = *(uint32_t*)&h;
            g_Wtl[n * 64 + j] = *(uint32_t*)&l;
        }
        if (t == 0) g_done_w = 0;
    }
}

// ---------------- 3. degree + count ------------------------------------------
__global__ void __launch_bounds__(256)
count_kernel(const void* __restrict__ ei, const float* __restrict__ ew) {
    int e = blockIdx.x * blockDim.x + threadIdx.x;
    if (e < N_EDGES) {
        int is64 = g_is64;
        int c = load_idx(ei, (long long)N_EDGES + e, is64);
        atomicAdd(&g_dinv[c], ew[e]);
        atomicAdd(&g_cnt[c], 1);
    }
}

// ---------------- 4. scan + last-block block-sum scan -----------------------
__global__ void __launch_bounds__(1024)
scan_a() {
    __shared__ int warpsum[48];
    __shared__ bool is_last;
    int i = blockIdx.x * SCAN_B + threadIdx.x;
    int lane = threadIdx.x & 31, wid = threadIdx.x >> 5;
    int v = 0;
    if (i < N_NODES) {
        v = g_cnt[i];
        g_cnt[i] = 0;
        g_dinv[i] = rsqrtf(g_dinv[i]);
    }
    int incl = v;
    #pragma unroll
    for (int o = 1; o < 32; o <<= 1) {
        int t = __shfl_up_sync(0xffffffffu, incl, o);
        if (lane >= o) incl += t;
    }
    if (lane == 31) warpsum[wid] = incl;
    __syncthreads();
    if (wid == 0) {
        int ws = warpsum[lane];
        int wincl = ws;
        #pragma unroll
        for (int o = 1; o < 32; o <<= 1) {
            int t = __shfl_up_sync(0xffffffffu, wincl, o);
            if (lane >= o) wincl += t;
        }
        warpsum[lane] = wincl - ws;
        if (lane == 31) g_bsum[blockIdx.x] = wincl;
    }
    __syncthreads();
    if (i < N_NODES) g_off[i] = warpsum[wid] + incl - v;

    __threadfence();
    if (threadIdx.x == 0) is_last = (atomicAdd(&g_done_s, 1) == gridDim.x - 1);
    __syncthreads();
    if (is_last) {
        int bincl = 0, bv = 0;
        if (threadIdx.x < 128) {
            bv = (threadIdx.x < N_SCAN_BLOCKS) ? g_bsum[threadIdx.x] : 0;
            bincl = bv;
            #pragma unroll
            for (int o = 1; o < 32; o <<= 1) {
                int t = __shfl_up_sync(0xffffffffu, bincl, o);
                if (lane >= o) bincl += t;
            }
            if (lane == 31) warpsum[32 + wid] = bincl;
        }
        __syncthreads();
        if (threadIdx.x < N_SCAN_BLOCKS) {
            int woff = 0;
            for (int w = 0; w < wid; w++) woff += warpsum[32 + w];
            g_boff[threadIdx.x] = woff + bincl - bv;
        }
        if (threadIdx.x == 0) g_done_s = 0;
    }
}

// ---------------- 5. CSR fill (packed int2) ----------------------------------
__global__ void __launch_bounds__(256)
fill_kernel(const void* __restrict__ ei, const float* __restrict__ ew) {
    int e = blockIdx.x * blockDim.x + threadIdx.x;
    if (e < N_EDGES) {
        int is64 = g_is64;
        int r = load_idx(ei, e, is64);
        int c = load_idx(ei, (long long)N_EDGES + e, is64);
        float nv = g_dinv[r] * ew[e] * g_dinv[c];
        int pos = g_off[c] + g_boff[c >> 10] + atomicAdd(&g_cnt[c], 1);
        g_csr[pos] = make_int2(r, __float_as_int(nv));
    }
}

// ---------------- 6. fused gather + bf16-split MMA + ReLU + cls -------------
__device__ __forceinline__ void mma_bf16(float& c0, float& c1, float& c2, float& c3,
                                         uint32_t a0, uint32_t a1, uint32_t a2, uint32_t a3,
                                         uint32_t b0, uint32_t b1) {
    asm volatile("mma.sync.aligned.m16n8k16.row.col.f32.bf16.bf16.f32 "
                 "{%0,%1,%2,%3}, {%4,%5,%6,%7}, {%8,%9}, {%0,%1,%2,%3};"
                 : "+f"(c0), "+f"(c1), "+f"(c2), "+f"(c3)
                 : "r"(a0), "r"(a1), "r"(a2), "r"(a3), "r"(b0), "r"(b1));
}

#define LDW 68   // padded row width in u32 -> conflict-free LDS

__device__ __forceinline__ float4 gacc4(float4 a, float n, float4 v) {
    a.x += n * v.x; a.y += n * v.y; a.z += n * v.z; a.w += n * v.w;
    return a;
}

__global__ void __launch_bounds__(256, 2)
final_kernel(const float* __restrict__ x,
             const float* __restrict__ clsw,
             const float* __restrict__ clsb,
             float* __restrict__ out) {
    extern __shared__ char sh[];
    uint32_t* sWh = (uint32_t*)sh;                        // [128][LDW]
    uint32_t* sWl = sWh + C * LDW;                        // [128][LDW]
    uint32_t* xsh = sWl + C * LDW;                        // [64][LDW]
    uint32_t* xsl = xsh + 64 * LDW;                       // [64][LDW]
    float*    scw = (float*)(xsl + 64 * LDW);             // [128]
    float*    spart = scw + C;                            // [2][64]

    const int tid = threadIdx.x;
    const int warp = tid >> 5, lane = tid & 31;
    const int g = lane >> 2, t = lane & 3;

    // ---- stage W hi/lo + cls weights ----
    for (int i = tid; i < C * (C / 2); i += 256) {
        int n = i >> 6, j = i & 63;
        sWh[n * LDW + j] = g_Wth[i];
        sWl[n * LDW + j] = g_Wtl[i];
    }
    if (tid < C) scw[tid] = clsw[tid];
    __syncthreads();

    // ---- gather: 8 rows per warp as 4 interleaved pairs; x8 clamped batch ----
    const int row0 = blockIdx.x * 64;
    const int n0w = row0 + warp * 8;
    const float4* x4 = (const float4*)x;

    int offv = N_EDGES;
    if (lane < 9) {
        int nn = n0w + lane;
        offv = (nn < N_NODES) ? (g_off[nn] + g_boff[nn >> 10]) : N_EDGES;
    }

    #pragma unroll
    for (int rp = 0; rp < 4; rp++) {
        const int la = warp * 8 + 2 * rp, lb = la + 1;
        const int na = row0 + la, nb = row0 + lb;
        int begA = __shfl_sync(0xffffffffu, offv, 2 * rp);
        int endA = __shfl_sync(0xffffffffu, offv, 2 * rp + 1);
        int begB = endA;
        int endB = __shfl_sync(0xffffffffu, offv, 2 * rp + 2);

        // self-loop loads for both rows (independent)
        float4 accA = make_float4(0.f, 0.f, 0.f, 0.f);
        float4 accB = make_float4(0.f, 0.f, 0.f, 0.f);
        if (na < N_NODES) {
            float dv = g_dinv[na];
            accA = gacc4(accA, dv * dv, x4[(size_t)na * 32 + lane]);
        }
        if (nb < N_NODES) {
            float dv = g_dinv[nb];
            accB = gacc4(accB, dv * dv, x4[(size_t)nb * 32 + lane]);
        }

        // one clamped x8 csr batch per row, both rows' loads issued together
        int2 ca[8], cb[8];
        bool hasA = begA < endA, hasB = begB < endB;
        #pragma unroll
        for (int i = 0; i < 8; i++) {
            int kA = begA + i; kA = (kA < endA) ? kA : endA - 1;
            ca[i] = hasA ? g_csr[kA] : make_int2(0, 0);
        }
        #pragma unroll
        for (int i = 0; i < 8; i++) {
            int kB = begB + i; kB = (kB < endB) ? kB : endB - 1;
            cb[i] = hasB ? g_csr[kB] : make_int2(0, 0);
        }
        // feature loads for both rows (16 gathers in flight)
        float4 va[8], vb[8];
        #pragma unroll
        for (int i = 0; i < 8; i++) va[i] = x4[(size_t)ca[i].x * 32 + lane];
        #pragma unroll
        for (int i = 0; i < 8; i++) vb[i] = x4[(size_t)cb[i].x * 32 + lane];
        // accumulate with clamped-duplicate masking
        #pragma unroll
        for (int i = 0; i < 8; i++) {
            float mA = (hasA && begA + i < endA) ? __int_as_float(ca[i].y) : 0.f;
            float mB = (hasB && begB + i < endB) ? __int_as_float(cb[i].y) : 0.f;
            accA = gacc4(accA, mA, va[i]);
            accB = gacc4(accB, mB, vb[i]);
        }
        // rare overflow: degree > 8
        for (int k = begA + 8; k < endA; k++) {
            int2 c = g_csr[k];
            accA = gacc4(accA, __int_as_float(c.y), x4[(size_t)c.x * 32 + lane]);
        }
        for (int k = begB + 8; k < endB; k++) {
            int2 c = g_csr[k];
            accB = gacc4(accB, __int_as_float(c.y), x4[(size_t)c.x * 32 + lane]);
        }

        // pack both rows to bf16 hi/lo smem
        {
            __nv_bfloat162 h0 = __floats2bfloat162_rn(accA.x, accA.y);
            __nv_bfloat162 h1 = __floats2bfloat162_rn(accA.z, accA.w);
            float2 f0 = __bfloat1622float2(h0), f1 = __bfloat1622float2(h1);
            __nv_bfloat162 l0 = __floats2bfloat162_rn(accA.x - f0.x, accA.y - f0.y);
            __nv_bfloat162 l1 = __floats2bfloat162_rn(accA.z - f1.x, accA.w - f1.y);
            xsh[la * LDW + lane * 2]     = *(uint32_t*)&h0;
            xsh[la * LDW + lane * 2 + 1] = *(uint32_t*)&h1;
            xsl[la * LDW + lane * 2]     = *(uint32_t*)&l0;
            xsl[la * LDW + lane * 2 + 1] = *(uint32_t*)&l1;
        }
        {
            __nv_bfloat162 h0 = __floats2bfloat162_rn(accB.x, accB.y);
            __nv_bfloat162 h1 = __floats2bfloat162_rn(accB.z, accB.w);
            float2 f0 = __bfloat1622float2(h0), f1 = __bfloat1622float2(h1);
            __nv_bfloat162 l0 = __floats2bfloat162_rn(accB.x - f0.x, accB.y - f0.y);
            __nv_bfloat162 l1 = __floats2bfloat162_rn(accB.z - f1.x, accB.w - f1.y);
            xsh[lb * LDW + lane * 2]     = *(uint32_t*)&h0;
            xsh[lb * LDW + lane * 2 + 1] = *(uint32_t*)&h1;
            xsl[lb * LDW + lane * 2]     = *(uint32_t*)&l0;
            xsl[lb * LDW + lane * 2 + 1] = *(uint32_t*)&l1;
        }
    }

    // pair barrier: warps 2m, 2m+1 (tids 64m..64m+63)
    int m = warp >> 1, wn = warp & 1;
    asm volatile("bar.sync %0, %1;" :: "r"(m + 1), "r"(64) : "memory");

    // ---- MMA: 16 rows x 64 cols, K=128; D += Ah*Bh + Ah*Bl + Al*Bh ----
    const int m0 = m * 16;
    float acc[8][4];
    #pragma unroll
    for (int nt = 0; nt < 8; nt++)
        acc[nt][0] = acc[nt][1] = acc[nt][2] = acc[nt][3] = 0.f;

    #pragma unroll
    for (int kt = 0; kt < 8; kt++) {
        int abase = (m0 + g) * LDW + kt * 8 + t;
        uint32_t ah0 = xsh[abase],     ah1 = xsh[abase + 8 * LDW];
        uint32_t ah2 = xsh[abase + 4], ah3 = xsh[abase + 8 * LDW + 4];
        uint32_t al0 = xsl[abase],     al1 = xsl[abase + 8 * LDW];
        uint32_t al2 = xsl[abase + 4], al3 = xsl[abase + 8 * LDW + 4];
        #pragma unroll
        for (int nt = 0; nt < 8; nt++) {
            int n = wn * 64 + nt * 8 + g;
            int bbase = n * LDW + kt * 8 + t;
            uint32_t bh0 = sWh[bbase], bh1 = sWh[bbase + 4];
            uint32_t bl0 = sWl[bbase], bl1 = sWl[bbase + 4];
            mma_bf16(acc[nt][0], acc[nt][1], acc[nt][2], acc[nt][3],
                     ah0, ah1, ah2, ah3, bh0, bh1);
            mma_bf16(acc[nt][0], acc[nt][1], acc[nt][2], acc[nt][3],
                     ah0, ah1, ah2, ah3, bl0, bl1);
            mma_bf16(acc[nt][0], acc[nt][1], acc[nt][2], acc[nt][3],
                     al0, al1, al2, al3, bh0, bh1);
        }
    }

    // ---- epilogue: relu + cls partial dot, quad reduce ----
    float p0 = 0.f, p1 = 0.f;
    #pragma unroll
    for (int nt = 0; nt < 8; nt++) {
        int col = wn * 64 + nt * 8 + 2 * t;
        float w0 = scw[col], w1 = scw[col + 1];
        p0 += fmaxf(acc[nt][0], 0.f) * w0 + fmaxf(acc[nt][1], 0.f) * w1;
        p1 += fmaxf(acc[nt][2], 0.f) * w0 + fmaxf(acc[nt][3], 0.f) * w1;
    }
    p0 += __shfl_xor_sync(0xffffffffu, p0, 1);
    p0 += __shfl_xor_sync(0xffffffffu, p0, 2);
    p1 += __shfl_xor_sync(0xffffffffu, p1, 1);
    p1 += __shfl_xor_sync(0xffffffffu, p1, 2);
    if (t == 0) {
        spart[wn * 64 + m0 + g]     = p0;
        spart[wn * 64 + m0 + g + 8] = p1;
    }
    __syncthreads();

    if (tid < 64) {
        int row = row0 + tid;
        if (row < N_NODES)
            out[row] = spart[tid] + spart[64 + tid] + clsb[0];
    }
}

// ---------------- launcher ---------------------------------------------------
extern "C" void kernel_launch(void* const* d_in, const int* in_sizes, int n_in,
                              void* d_out, int out_size) {
    const float* x    = (const float*)d_in[0];
    const void*  ei   = d_in[1];
    const float* ew   = (const float*)d_in[2];
    const float* W0   = (const float*)d_in[3];
    const float* Wih  = (const float*)d_in[4];
    const float* Whh  = (const float*)d_in[5];
    const float* bih  = (const float*)d_in[6];
    const float* bhh  = (const float*)d_in[7];
    const float* clsw = (const float*)d_in[8];
    const float* clsb = (const float*)d_in[9];
    float* out = (float*)d_out;

    deg_init<<<(N_NODES + 255) / 256, 256>>>((const unsigned*)ei);
    gru_kernel<<<C, C>>>(W0, Wih, Whh, bih, bhh);
    count_kernel<<<CNT_BLOCKS, 256>>>(ei, ew);
    scan_a<<<N_SCAN_BLOCKS, SCAN_B>>>();
    fill_kernel<<<CNT_BLOCKS, 256>>>(ei, ew);

    const int SMEM = (2 * C * LDW + 2 * 64 * LDW) * 4 + (C + 128) * 4;  // ~103 KB
    cudaFuncSetAttribute(final_kernel, cudaFuncAttributeMaxDynamicSharedMemorySize, SMEM);
    final_kernel<<<(N_NODES + 63) / 64, 256, SMEM>>>(x, clsw, clsb, out);
}